// round 8
// baseline (speedup 1.0000x reference)
#include <cuda_runtime.h>
#include <cuda_bf16.h>
#include <cstdint>

#define N_NODES  100000
#define N_EDGES  1600000
#define N_GRAPHS 50
#define FDIM     128

// Scratch
__device__ __align__(128) float g_agg[2][(size_t)N_NODES * FDIM];
__device__ __align__(128) float g_gproj[N_GRAPHS * FDIM];
__device__ __align__(128) __nv_bfloat16 g_Whi[3 * FDIM * FDIM];
__device__ __align__(128) __nv_bfloat16 g_Wlo[3 * FDIM * FDIM];
// counting sort by receiver
__device__ int  g_cnt[N_NODES];
__device__ int  g_start[N_NODES];
__device__ int  g_cursor[N_NODES];   // after binning: == segment end
__device__ __align__(16) int2 g_idx[N_EDGES];  // (edge_id, send[edge])

// ---------------------------------------------------------------------------
// helpers
// ---------------------------------------------------------------------------
__device__ __forceinline__ unsigned smem_u32(const void* p) {
    unsigned a;
    asm("{ .reg .u64 t; cvta.to.shared.u64 t, %1; cvt.u32.u64 %0, t; }"
        : "=r"(a) : "l"(p));
    return a;
}
__device__ __forceinline__ unsigned pbf2(float lo, float hi) {
    unsigned r;
    asm("cvt.rn.bf16x2.f32 %0, %1, %2;" : "=r"(r) : "f"(hi), "f"(lo));
    return r;
}
__device__ __forceinline__ void ldsm4(unsigned* r, unsigned addr) {
    asm volatile("ldmatrix.sync.aligned.m8n8.x4.shared.b16 {%0,%1,%2,%3}, [%4];"
                 : "=r"(r[0]), "=r"(r[1]), "=r"(r[2]), "=r"(r[3]) : "r"(addr));
}
__device__ __forceinline__ void mma_bf16(float* c, const unsigned* a,
                                         const unsigned* b) {
    asm volatile(
        "mma.sync.aligned.m16n8k16.row.col.f32.bf16.bf16.f32 "
        "{%0,%1,%2,%3}, {%4,%5,%6,%7}, {%8,%9}, {%0,%1,%2,%3};"
        : "+f"(c[0]), "+f"(c[1]), "+f"(c[2]), "+f"(c[3])
        : "r"(a[0]), "r"(a[1]), "r"(a[2]), "r"(a[3]), "r"(b[0]), "r"(b[1]));
}

// ---------------------------------------------------------------------------
// Zero agg[1] (send accumulators; recv side is written directly) + histogram
// ---------------------------------------------------------------------------
__global__ void zero_kernel() {
    size_t n = ((size_t)N_NODES * FDIM) / 4;
    float4* p = (float4*)g_agg[1];
    float4 z = make_float4(0.f, 0.f, 0.f, 0.f);
    for (size_t i = (size_t)blockIdx.x * blockDim.x + threadIdx.x; i < n;
         i += (size_t)gridDim.x * blockDim.x)
        p[i] = z;
    for (size_t i = (size_t)blockIdx.x * blockDim.x + threadIdx.x; i < N_NODES;
         i += (size_t)gridDim.x * blockDim.x)
        g_cnt[i] = 0;
}

// ---------------------------------------------------------------------------
// Counting sort, step 1: histogram of receivers
// ---------------------------------------------------------------------------
__global__ void hist_kernel(const int* __restrict__ recv) {
    int e = blockIdx.x * blockDim.x + threadIdx.x;
    if (e < N_EDGES) atomicAdd(&g_cnt[__ldg(&recv[e])], 1);
}

// ---------------------------------------------------------------------------
// Counting sort, step 2: exclusive prefix scan (single block, 1024 threads)
// ---------------------------------------------------------------------------
__global__ __launch_bounds__(1024) void scan_kernel() {
    __shared__ int ssum[1024];
    const int t = threadIdx.x;
    const int CH = (N_NODES + 1023) / 1024;  // 98
    const int base = t * CH;
    int s = 0;
    for (int i = 0; i < CH; i++) {
        int n = base + i;
        if (n < N_NODES) s += g_cnt[n];
    }
    ssum[t] = s;
    __syncthreads();
    for (int off = 1; off < 1024; off <<= 1) {
        int v = (t >= off) ? ssum[t - off] : 0;
        __syncthreads();
        ssum[t] += v;
        __syncthreads();
    }
    int ex = ssum[t] - s;  // exclusive prefix of this chunk
    for (int i = 0; i < CH; i++) {
        int n = base + i;
        if (n < N_NODES) {
            g_start[n] = ex;
            g_cursor[n] = ex;
            ex += g_cnt[n];
        }
    }
}

// ---------------------------------------------------------------------------
// Counting sort, step 3: bin edge ids (paired with send[]) by receiver
// ---------------------------------------------------------------------------
__global__ void bin_kernel(const int* __restrict__ recv,
                           const int* __restrict__ send) {
    int e = blockIdx.x * blockDim.x + threadIdx.x;
    if (e >= N_EDGES) return;
    int r = __ldg(&recv[e]);
    int pos = atomicAdd(&g_cursor[r], 1);
    g_idx[pos] = make_int2(e, __ldg(&send[e]));
}

// ---------------------------------------------------------------------------
// Gather+scatter: warp per receiver node.
// recv direction: register accumulate + single store (no atomics, no zeroing).
// send direction: red.v4 into L2-resident 51MB agg[1] (evict_last policy).
// ---------------------------------------------------------------------------
__global__ __launch_bounds__(256) void gather_kernel(
    const float4* __restrict__ ef) {
    const int n = blockIdx.x * 8 + (threadIdx.x >> 5);
    if (n >= N_NODES) return;
    const int lane = threadIdx.x & 31;

    unsigned long long pol_last, pol_first;
    asm("createpolicy.fractional.L2::evict_last.b64 %0, 1.0;" : "=l"(pol_last));
    asm("createpolicy.fractional.L2::evict_first.b64 %0, 1.0;" : "=l"(pol_first));

    const int j0 = __ldg(&g_start[n]);
    const int j1 = __ldg(&g_cursor[n]);  // == segment end after binning

    float4 acc = make_float4(0.f, 0.f, 0.f, 0.f);
#pragma unroll 2
    for (int j = j0; j < j1; j++) {
        int2 p = __ldg(&g_idx[j]);  // broadcast across warp
        float4 v;
        asm volatile("ld.global.nc.L2::cache_hint.v4.f32 {%0,%1,%2,%3}, [%4], %5;"
                     : "=f"(v.x), "=f"(v.y), "=f"(v.z), "=f"(v.w)
                     : "l"(&ef[(size_t)p.x * (FDIM / 4) + lane]), "l"(pol_first));
        acc.x += v.x; acc.y += v.y; acc.z += v.z; acc.w += v.w;
        float* ps = &g_agg[1][(size_t)p.y * FDIM + lane * 4];
        asm volatile("red.global.add.L2::cache_hint.v4.f32 [%0], {%1,%2,%3,%4}, %5;"
                     :: "l"(ps), "f"(v.x), "f"(v.y), "f"(v.z), "f"(v.w),
                        "l"(pol_last)
                     : "memory");
    }
    *(float4*)&g_agg[0][(size_t)n * FDIM + lane * 4] = acc;
}

// ---------------------------------------------------------------------------
// Split weights into bf16 hi/lo
// ---------------------------------------------------------------------------
__global__ void wsplit_kernel(const float* __restrict__ Wn,
                              const float* __restrict__ Wi,
                              const float* __restrict__ Wo) {
    int i = blockIdx.x * blockDim.x + threadIdx.x;
    if (i >= 3 * FDIM * FDIM) return;
    const float* W[3] = {Wn, Wi, Wo};
    float w = W[i >> 14][i & 16383];
    __nv_bfloat16 h = __float2bfloat16_rn(w);
    g_Whi[i] = h;
    g_Wlo[i] = __float2bfloat16_rn(w - __bfloat162float(h));
}

// ---------------------------------------------------------------------------
// Project globals: g_gproj[g][j] = dot(G[g], Wg[j]) + bias[j]  (fp32 exact)
// ---------------------------------------------------------------------------
__global__ void gproj_kernel(const float* __restrict__ gf,
                             const float* __restrict__ Wg,
                             const float* __restrict__ bias) {
    __shared__ float s[FDIM];
    int g = blockIdx.x, j = threadIdx.x;
    s[j] = gf[g * FDIM + j];
    __syncthreads();
    const float4* wrow = (const float4*)(Wg + (size_t)j * FDIM);
    float acc = 0.f;
#pragma unroll
    for (int k = 0; k < FDIM / 4; k++) {
        float4 w = wrow[k];
        const float4 a = *(const float4*)&s[k * 4];
        acc += a.x * w.x + a.y * w.y + a.z * w.z + a.w * w.w;
    }
    g_gproj[g * FDIM + j] = acc + bias[j];
}

// ---------------------------------------------------------------------------
// mma.sync bf16 split-3 GEMM (unchanged from R4/R7 WIN).
// ---------------------------------------------------------------------------
#define TOFF(r, kk) (((r) >> 3) * 512 + ((kk) >> 3) * 128 + ((r)&7) * 16 + ((kk)&7) * 2)

__global__ __launch_bounds__(256, 1) void gemm_kernel(
    const float* __restrict__ node,
    const int* __restrict__ gidx,
    float* __restrict__ out) {
    __shared__ __align__(128) unsigned char sm[4 * 8192];
    const unsigned sA = smem_u32(sm);

    const int tid = threadIdx.x;
    const int wid = tid >> 5, lid = tid & 31;
    const int wm = wid & 3, wn = wid >> 2;
    const int m0 = blockIdx.x * 128;

    const int t8 = lid >> 3, r8 = lid & 7;
    const unsigned aOff = (unsigned)TOFF(wm * 32 + (t8 & 1) * 8 + r8, (t8 >> 1) * 8);
    const unsigned bOff = (unsigned)TOFF(wn * 64 + (t8 >> 1) * 8 + r8, (t8 & 1) * 8);

    const unsigned aHi = sA + aOff;
    const unsigned bHi = sA + 16384 + bOff;

    float acc[2][8][4];
#pragma unroll
    for (int i = 0; i < 2; i++)
#pragma unroll
        for (int j = 0; j < 8; j++)
#pragma unroll
            for (int q = 0; q < 4; q++) acc[i][j][q] = 0.f;

    const float* Asrc[3] = {node, g_agg[0], g_agg[1]};

    const int frow = tid >> 1;
    const int fkh = (tid & 1) * 16;
    int arow_g = m0 + frow;
    if (arow_g >= N_NODES) arow_g = N_NODES - 1;

#pragma unroll 1
    for (int ch = 0; ch < 12; ch++) {
        const int p = ch >> 2;
        const int kc = (ch & 3) * 32;

        __syncthreads();
        {
            const float* ap = Asrc[p] + (size_t)arow_g * FDIM + kc + fkh;
#pragma unroll
            for (int g = 0; g < 2; g++) {
                float4 f0 = *(const float4*)(ap + g * 8);
                float4 f1 = *(const float4*)(ap + g * 8 + 4);
                __nv_bfloat16 h0 = __float2bfloat16_rn(f0.x);
                __nv_bfloat16 h1 = __float2bfloat16_rn(f0.y);
                __nv_bfloat16 h2 = __float2bfloat16_rn(f0.z);
                __nv_bfloat16 h3 = __float2bfloat16_rn(f0.w);
                __nv_bfloat16 h4 = __float2bfloat16_rn(f1.x);
                __nv_bfloat16 h5 = __float2bfloat16_rn(f1.y);
                __nv_bfloat16 h6 = __float2bfloat16_rn(f1.z);
                __nv_bfloat16 h7 = __float2bfloat16_rn(f1.w);
                uint4 vh;
                vh.x = ((unsigned)__bfloat16_as_ushort(h1) << 16) | __bfloat16_as_ushort(h0);
                vh.y = ((unsigned)__bfloat16_as_ushort(h3) << 16) | __bfloat16_as_ushort(h2);
                vh.z = ((unsigned)__bfloat16_as_ushort(h5) << 16) | __bfloat16_as_ushort(h4);
                vh.w = ((unsigned)__bfloat16_as_ushort(h7) << 16) | __bfloat16_as_ushort(h6);
                uint4 vl;
                vl.x = pbf2(f0.x - __bfloat162float(h0), f0.y - __bfloat162float(h1));
                vl.y = pbf2(f0.z - __bfloat162float(h2), f0.w - __bfloat162float(h3));
                vl.z = pbf2(f1.x - __bfloat162float(h4), f1.y - __bfloat162float(h5));
                vl.w = pbf2(f1.z - __bfloat162float(h6), f1.w - __bfloat162float(h7));
                unsigned off = (unsigned)((frow >> 3) * 512 + ((fkh >> 3) + g) * 128 +
                                          (frow & 7) * 16);
                *(uint4*)(sm + off) = vh;
                *(uint4*)(sm + 8192 + off) = vl;
            }
        }
        {
            const unsigned char* bh = (const unsigned char*)g_Whi +
                ((size_t)p * FDIM * FDIM + (size_t)frow * FDIM + kc + fkh) * 2;
            const unsigned char* bl = (const unsigned char*)g_Wlo +
                ((size_t)p * FDIM * FDIM + (size_t)frow * FDIM + kc + fkh) * 2;
#pragma unroll
            for (int g = 0; g < 2; g++) {
                uint4 vh = *(const uint4*)(bh + g * 16);
                uint4 vl = *(const uint4*)(bl + g * 16);
                unsigned off = (unsigned)((frow >> 3) * 512 + ((fkh >> 3) + g) * 128 +
                                          (frow & 7) * 16);
                *(uint4*)(sm + 16384 + off) = vh;
                *(uint4*)(sm + 24576 + off) = vl;
            }
        }
        __syncthreads();

#pragma unroll
        for (int ks = 0; ks < 2; ks++) {
            const unsigned kso = ks * 256;
            unsigned ah[2][4], al[2][4];
            ldsm4(ah[0], aHi + kso);
            ldsm4(ah[1], aHi + 1024 + kso);
            ldsm4(al[0], aHi + 8192 + kso);
            ldsm4(al[1], aHi + 9216 + kso);
#pragma unroll
            for (int np = 0; np < 4; np++) {
                unsigned bh[4], bl[4];
                ldsm4(bh, bHi + np * 1024 + kso);
                ldsm4(bl, bHi + 8192 + np * 1024 + kso);
#pragma unroll
                for (int mt = 0; mt < 2; mt++) {
                    mma_bf16(acc[mt][np * 2], ah[mt], bh);
                    mma_bf16(acc[mt][np * 2 + 1], ah[mt], bh + 2);
                    mma_bf16(acc[mt][np * 2], ah[mt], bl);
                    mma_bf16(acc[mt][np * 2 + 1], ah[mt], bl + 2);
                    mma_bf16(acc[mt][np * 2], al[mt], bh);
                    mma_bf16(acc[mt][np * 2 + 1], al[mt], bh + 2);
                }
            }
        }
    }

    const int quad = lid >> 2, qlane = lid & 3;
#pragma unroll
    for (int mt = 0; mt < 2; mt++) {
        const int r0 = m0 + wm * 32 + mt * 16 + quad;
        const int r1 = r0 + 8;
        const bool ok0 = r0 < N_NODES, ok1 = r1 < N_NODES;
        const float* gp0 = g_gproj + (size_t)(ok0 ? __ldg(&gidx[r0]) : 0) * FDIM;
        const float* gp1 = g_gproj + (size_t)(ok1 ? __ldg(&gidx[r1]) : 0) * FDIM;
#pragma unroll
        for (int nt = 0; nt < 8; nt++) {
            const int col = wn * 64 + nt * 8 + qlane * 2;
            if (ok0) {
                float2 g0 = *(const float2*)(gp0 + col);
                float2 o0 = make_float2(acc[mt][nt][0] + g0.x, acc[mt][nt][1] + g0.y);
                *(float2*)(out + (size_t)r0 * FDIM + col) = o0;
            }
            if (ok1) {
                float2 g1 = *(const float2*)(gp1 + col);
                float2 o1 = make_float2(acc[mt][nt][2] + g1.x, acc[mt][nt][3] + g1.y);
                *(float2*)(out + (size_t)r1 * FDIM + col) = o1;
            }
        }
    }
}

// ---------------------------------------------------------------------------
// Launch
// ---------------------------------------------------------------------------
extern "C" void kernel_launch(void* const* d_in, const int* in_sizes, int n_in,
                              void* d_out, int out_size) {
    const float* node_features   = (const float*)d_in[0];
    const float* edge_features   = (const float*)d_in[1];
    const float* global_features = (const float*)d_in[2];
    const float* W_node     = (const float*)d_in[3];
    const float* W_incoming = (const float*)d_in[4];
    const float* W_outgoing = (const float*)d_in[5];
    const float* W_global   = (const float*)d_in[6];
    const float* bias       = (const float*)d_in[7];
    const int*   receivers  = (const int*)d_in[8];
    const int*   senders    = (const int*)d_in[9];
    const int*   graph_idx  = (const int*)d_in[10];
    float* out = (float*)d_out;

    zero_kernel<<<1024, 256>>>();
    wsplit_kernel<<<(3 * FDIM * FDIM + 255) / 256, 256>>>(W_node, W_incoming,
                                                          W_outgoing);
    gproj_kernel<<<N_GRAPHS, FDIM>>>(global_features, W_global, bias);

    hist_kernel<<<(N_EDGES + 255) / 256, 256>>>(receivers);
    scan_kernel<<<1, 1024>>>();
    bin_kernel<<<(N_EDGES + 255) / 256, 256>>>(receivers, senders);
    gather_kernel<<<(N_NODES + 7) / 8, 256>>>((const float4*)edge_features);

    {
        int grid = (N_NODES + 127) / 128;  // 782
        gemm_kernel<<<grid, 256>>>(node_features, graph_idx, out);
    }
}

// round 13
// speedup vs baseline: 1.0472x; 1.0472x over previous
#include <cuda_runtime.h>
#include <cuda_bf16.h>
#include <cstdint>

#define N_NODES  100000
#define N_EDGES  1600000
#define N_GRAPHS 50
#define FDIM     128

// Scratch
__device__ __align__(128) float g_agg[2][(size_t)N_NODES * FDIM];
__device__ __align__(128) float g_gproj[N_GRAPHS * FDIM];
__device__ __align__(128) __nv_bfloat16 g_Whi[3 * FDIM * FDIM];
__device__ __align__(128) __nv_bfloat16 g_Wlo[3 * FDIM * FDIM];

// ---------------------------------------------------------------------------
// helpers
// ---------------------------------------------------------------------------
__device__ __forceinline__ unsigned smem_u32(const void* p) {
    unsigned a;
    asm("{ .reg .u64 t; cvta.to.shared.u64 t, %1; cvt.u32.u64 %0, t; }"
        : "=r"(a) : "l"(p));
    return a;
}
__device__ __forceinline__ unsigned pbf2(float lo, float hi) {
    unsigned r;
    asm("cvt.rn.bf16x2.f32 %0, %1, %2;" : "=r"(r) : "f"(hi), "f"(lo));
    return r;
}
__device__ __forceinline__ void ldsm4(unsigned* r, unsigned addr) {
    asm volatile("ldmatrix.sync.aligned.m8n8.x4.shared.b16 {%0,%1,%2,%3}, [%4];"
                 : "=r"(r[0]), "=r"(r[1]), "=r"(r[2]), "=r"(r[3]) : "r"(addr));
}
__device__ __forceinline__ void mma_bf16(float* c, const unsigned* a,
                                         const unsigned* b) {
    asm volatile(
        "mma.sync.aligned.m16n8k16.row.col.f32.bf16.bf16.f32 "
        "{%0,%1,%2,%3}, {%4,%5,%6,%7}, {%8,%9}, {%0,%1,%2,%3};"
        : "+f"(c[0]), "+f"(c[1]), "+f"(c[2]), "+f"(c[3])
        : "r"(a[0]), "r"(a[1]), "r"(a[2]), "r"(a[3]), "r"(b[0]), "r"(b[1]));
}

// ---------------------------------------------------------------------------
// Zero + L2-prime the aggregation buffers (evict_last stores plant the 102MB
// destination set resident in L2 before the scatter touches it)
// ---------------------------------------------------------------------------
__global__ void zero_kernel() {
    unsigned long long pol;
    asm("createpolicy.fractional.L2::evict_last.b64 %0, 1.0;" : "=l"(pol));
    size_t n = ((size_t)2 * N_NODES * FDIM) / 4;
    float4* p = (float4*)g_agg;
    for (size_t i = (size_t)blockIdx.x * blockDim.x + threadIdx.x; i < n;
         i += (size_t)gridDim.x * blockDim.x) {
        asm volatile("st.global.L2::cache_hint.v4.f32 [%0], {%1,%2,%3,%4}, %5;"
                     :: "l"(p + i), "f"(0.f), "f"(0.f), "f"(0.f), "f"(0.f),
                        "l"(pol) : "memory");
    }
}

// ---------------------------------------------------------------------------
// Split weights into bf16 hi/lo
// ---------------------------------------------------------------------------
__global__ void wsplit_kernel(const float* __restrict__ Wn,
                              const float* __restrict__ Wi,
                              const float* __restrict__ Wo) {
    int i = blockIdx.x * blockDim.x + threadIdx.x;
    if (i >= 3 * FDIM * FDIM) return;
    const float* W[3] = {Wn, Wi, Wo};
    float w = W[i >> 14][i & 16383];
    __nv_bfloat16 h = __float2bfloat16_rn(w);
    g_Whi[i] = h;
    g_Wlo[i] = __float2bfloat16_rn(w - __bfloat162float(h));
}

// ---------------------------------------------------------------------------
// Project globals: g_gproj[g][j] = dot(G[g], Wg[j]) + bias[j]  (fp32 exact)
// ---------------------------------------------------------------------------
__global__ void gproj_kernel(const float* __restrict__ gf,
                             const float* __restrict__ Wg,
                             const float* __restrict__ bias) {
    __shared__ float s[FDIM];
    int g = blockIdx.x, j = threadIdx.x;
    s[j] = gf[g * FDIM + j];
    __syncthreads();
    const float4* wrow = (const float4*)(Wg + (size_t)j * FDIM);
    float acc = 0.f;
#pragma unroll
    for (int k = 0; k < FDIM / 4; k++) {
        float4 w = wrow[k];
        const float4 a = *(const float4*)&s[k * 4];
        acc += a.x * w.x + a.y * w.y + a.z * w.z + a.w * w.w;
    }
    g_gproj[g * FDIM + j] = acc + bias[j];
}

// ---------------------------------------------------------------------------
// Scatter-add: warp per edge, red.v4.f32 (R7 WIN version).
// ---------------------------------------------------------------------------
__global__ void scatter_kernel(const float4* __restrict__ ef,
                               const int* __restrict__ recv,
                               const int* __restrict__ send) {
    int w = (int)((blockIdx.x * (size_t)blockDim.x + threadIdx.x) >> 5);
    int lane = threadIdx.x & 31;
    if (w >= N_EDGES) return;

    unsigned long long pol_last, pol_first;
    asm("createpolicy.fractional.L2::evict_last.b64 %0, 1.0;" : "=l"(pol_last));
    asm("createpolicy.fractional.L2::evict_first.b64 %0, 1.0;" : "=l"(pol_first));

    float4 v;
    asm volatile("ld.global.nc.L2::cache_hint.v4.f32 {%0,%1,%2,%3}, [%4], %5;"
                 : "=f"(v.x), "=f"(v.y), "=f"(v.z), "=f"(v.w)
                 : "l"(&ef[(size_t)w * (FDIM / 4) + lane]), "l"(pol_first));
    int r = __ldg(&recv[w]);
    int s = __ldg(&send[w]);
    float* pr = &g_agg[0][(size_t)r * FDIM + lane * 4];
    float* ps = &g_agg[1][(size_t)s * FDIM + lane * 4];
    asm volatile("red.global.add.L2::cache_hint.v4.f32 [%0], {%1,%2,%3,%4}, %5;"
                 :: "l"(pr), "f"(v.x), "f"(v.y), "f"(v.z), "f"(v.w), "l"(pol_last)
                 : "memory");
    asm volatile("red.global.add.L2::cache_hint.v4.f32 [%0], {%1,%2,%3,%4}, %5;"
                 :: "l"(ps), "f"(v.x), "f"(v.y), "f"(v.z), "f"(v.w), "l"(pol_last)
                 : "memory");
}

// ---------------------------------------------------------------------------
// mma.sync bf16 split-3 GEMM, software-pipelined: global loads for chunk c+1
// issue right after the smem commit of chunk c, overlapping LDG latency with
// the 48-HMMA compute block.
// ---------------------------------------------------------------------------
#define TOFF(r, kk) (((r) >> 3) * 512 + ((kk) >> 3) * 128 + ((r)&7) * 16 + ((kk)&7) * 2)

__global__ __launch_bounds__(256) void gemm_kernel(
    const float* __restrict__ node,
    const int* __restrict__ gidx,
    float* __restrict__ out) {
    __shared__ __align__(128) unsigned char sm[4 * 8192];
    const unsigned sA = smem_u32(sm);

    const int tid = threadIdx.x;
    const int wid = tid >> 5, lid = tid & 31;
    const int wm = wid & 3, wn = wid >> 2;
    const int m0 = blockIdx.x * 128;

    const int t8 = lid >> 3, r8 = lid & 7;
    const unsigned aOff = (unsigned)TOFF(wm * 32 + (t8 & 1) * 8 + r8, (t8 >> 1) * 8);
    const unsigned bOff = (unsigned)TOFF(wn * 64 + (t8 >> 1) * 8 + r8, (t8 & 1) * 8);

    const unsigned aHi = sA + aOff;
    const unsigned bHi = sA + 16384 + bOff;

    float acc[2][8][4];
#pragma unroll
    for (int i = 0; i < 2; i++)
#pragma unroll
        for (int j = 0; j < 8; j++)
#pragma unroll
            for (int q = 0; q < 4; q++) acc[i][j][q] = 0.f;

    const float* Asrc[3] = {node, g_agg[0], g_agg[1]};

    const int frow = tid >> 1;
    const int fkh = (tid & 1) * 16;
    int arow_g = m0 + frow;
    if (arow_g >= N_NODES) arow_g = N_NODES - 1;

    // smem store offsets (ch-independent)
    const unsigned soff0 = (unsigned)((frow >> 3) * 512 + (fkh >> 3) * 128 +
                                      (frow & 7) * 16);
    const unsigned soff1 = soff0 + 128;

    // prefetch registers
    float4 fa[4];
    uint4 wbh[2], wbl[2];

#define LOADG(CH)                                                              \
    {                                                                          \
        const int p_ = (CH) >> 2;                                              \
        const int kc_ = ((CH)&3) * 32;                                         \
        const float* ap_ = Asrc[p_] + (size_t)arow_g * FDIM + kc_ + fkh;       \
        fa[0] = *(const float4*)(ap_);                                         \
        fa[1] = *(const float4*)(ap_ + 4);                                     \
        fa[2] = *(const float4*)(ap_ + 8);                                     \
        fa[3] = *(const float4*)(ap_ + 12);                                    \
        const unsigned char* bh_ = (const unsigned char*)g_Whi +               \
            ((size_t)p_ * FDIM * FDIM + (size_t)frow * FDIM + kc_ + fkh) * 2;  \
        const unsigned char* bl_ = (const unsigned char*)g_Wlo +               \
            ((size_t)p_ * FDIM * FDIM + (size_t)frow * FDIM + kc_ + fkh) * 2;  \
        wbh[0] = *(const uint4*)(bh_);                                         \
        wbh[1] = *(const uint4*)(bh_ + 16);                                    \
        wbl[0] = *(const uint4*)(bl_);                                         \
        wbl[1] = *(const uint4*)(bl_ + 16);                                    \
    }

    LOADG(0);

#pragma unroll 1
    for (int ch = 0; ch < 12; ch++) {
        __syncthreads();
        // ---- commit prefetched regs to smem (convert A to hi/lo) ----
#pragma unroll
        for (int g = 0; g < 2; g++) {
            float4 f0 = fa[g * 2], f1 = fa[g * 2 + 1];
            __nv_bfloat16 h0 = __float2bfloat16_rn(f0.x);
            __nv_bfloat16 h1 = __float2bfloat16_rn(f0.y);
            __nv_bfloat16 h2 = __float2bfloat16_rn(f0.z);
            __nv_bfloat16 h3 = __float2bfloat16_rn(f0.w);
            __nv_bfloat16 h4 = __float2bfloat16_rn(f1.x);
            __nv_bfloat16 h5 = __float2bfloat16_rn(f1.y);
            __nv_bfloat16 h6 = __float2bfloat16_rn(f1.z);
            __nv_bfloat16 h7 = __float2bfloat16_rn(f1.w);
            uint4 vh;
            vh.x = ((unsigned)__bfloat16_as_ushort(h1) << 16) | __bfloat16_as_ushort(h0);
            vh.y = ((unsigned)__bfloat16_as_ushort(h3) << 16) | __bfloat16_as_ushort(h2);
            vh.z = ((unsigned)__bfloat16_as_ushort(h5) << 16) | __bfloat16_as_ushort(h4);
            vh.w = ((unsigned)__bfloat16_as_ushort(h7) << 16) | __bfloat16_as_ushort(h6);
            uint4 vl;
            vl.x = pbf2(f0.x - __bfloat162float(h0), f0.y - __bfloat162float(h1));
            vl.y = pbf2(f0.z - __bfloat162float(h2), f0.w - __bfloat162float(h3));
            vl.z = pbf2(f1.x - __bfloat162float(h4), f1.y - __bfloat162float(h5));
            vl.w = pbf2(f1.z - __bfloat162float(h6), f1.w - __bfloat162float(h7));
            unsigned off = g ? soff1 : soff0;
            *(uint4*)(sm + off) = vh;
            *(uint4*)(sm + 8192 + off) = vl;
            *(uint4*)(sm + 16384 + off) = wbh[g];
            *(uint4*)(sm + 24576 + off) = wbl[g];
        }
        __syncthreads();

        // ---- prefetch next chunk (overlaps with MMA below) ----
        if (ch < 11) LOADG(ch + 1);

        // ---- MMA over BK=32 (two k16 steps) ----
#pragma unroll
        for (int ks = 0; ks < 2; ks++) {
            const unsigned kso = ks * 256;
            unsigned ah[2][4], al[2][4];
            ldsm4(ah[0], aHi + kso);
            ldsm4(ah[1], aHi + 1024 + kso);
            ldsm4(al[0], aHi + 8192 + kso);
            ldsm4(al[1], aHi + 9216 + kso);
#pragma unroll
            for (int np = 0; np < 4; np++) {
                unsigned bh[4], bl[4];
                ldsm4(bh, bHi + np * 1024 + kso);
                ldsm4(bl, bHi + 8192 + np * 1024 + kso);
#pragma unroll
                for (int mt = 0; mt < 2; mt++) {
                    mma_bf16(acc[mt][np * 2], ah[mt], bh);
                    mma_bf16(acc[mt][np * 2 + 1], ah[mt], bh + 2);
                    mma_bf16(acc[mt][np * 2], ah[mt], bl);
                    mma_bf16(acc[mt][np * 2 + 1], ah[mt], bl + 2);
                    mma_bf16(acc[mt][np * 2], al[mt], bh);
                    mma_bf16(acc[mt][np * 2 + 1], al[mt], bh + 2);
                }
            }
        }
    }
#undef LOADG

    const int quad = lid >> 2, qlane = lid & 3;
#pragma unroll
    for (int mt = 0; mt < 2; mt++) {
        const int r0 = m0 + wm * 32 + mt * 16 + quad;
        const int r1 = r0 + 8;
        const bool ok0 = r0 < N_NODES, ok1 = r1 < N_NODES;
        const float* gp0 = g_gproj + (size_t)(ok0 ? __ldg(&gidx[r0]) : 0) * FDIM;
        const float* gp1 = g_gproj + (size_t)(ok1 ? __ldg(&gidx[r1]) : 0) * FDIM;
#pragma unroll
        for (int nt = 0; nt < 8; nt++) {
            const int col = wn * 64 + nt * 8 + qlane * 2;
            if (ok0) {
                float2 g0 = *(const float2*)(gp0 + col);
                float2 o0 = make_float2(acc[mt][nt][0] + g0.x, acc[mt][nt][1] + g0.y);
                *(float2*)(out + (size_t)r0 * FDIM + col) = o0;
            }
            if (ok1) {
                float2 g1 = *(const float2*)(gp1 + col);
                float2 o1 = make_float2(acc[mt][nt][2] + g1.x, acc[mt][nt][3] + g1.y);
                *(float2*)(out + (size_t)r1 * FDIM + col) = o1;
            }
        }
    }
}

// ---------------------------------------------------------------------------
// Launch
// ---------------------------------------------------------------------------
extern "C" void kernel_launch(void* const* d_in, const int* in_sizes, int n_in,
                              void* d_out, int out_size) {
    const float* node_features   = (const float*)d_in[0];
    const float* edge_features   = (const float*)d_in[1];
    const float* global_features = (const float*)d_in[2];
    const float* W_node     = (const float*)d_in[3];
    const float* W_incoming = (const float*)d_in[4];
    const float* W_outgoing = (const float*)d_in[5];
    const float* W_global   = (const float*)d_in[6];
    const float* bias       = (const float*)d_in[7];
    const int*   receivers  = (const int*)d_in[8];
    const int*   senders    = (const int*)d_in[9];
    const int*   graph_idx  = (const int*)d_in[10];
    float* out = (float*)d_out;

    zero_kernel<<<1024, 256>>>();
    wsplit_kernel<<<(3 * FDIM * FDIM + 255) / 256, 256>>>(W_node, W_incoming,
                                                          W_outgoing);
    gproj_kernel<<<N_GRAPHS, FDIM>>>(global_features, W_global, bias);

    {
        int threads = 256;
        long long total = (long long)N_EDGES * 32;
        int blocks = (int)((total + threads - 1) / threads);
        scatter_kernel<<<blocks, threads>>>((const float4*)edge_features,
                                            receivers, senders);
    }
    {
        int grid = (N_NODES + 127) / 128;  // 782
        gemm_kernel<<<grid, 256>>>(node_features, graph_idx, out);
    }
}

// round 14
// speedup vs baseline: 1.1669x; 1.1143x over previous
#include <cuda_runtime.h>
#include <cuda_bf16.h>
#include <cstdint>

#define N_NODES  100000
#define N_EDGES  1600000
#define N_GRAPHS 50
#define FDIM     128

// Scratch
__device__ __align__(128) float g_agg[2][(size_t)N_NODES * FDIM];
__device__ __align__(128) float g_gproj[N_GRAPHS * FDIM];
__device__ __align__(128) __nv_bfloat16 g_Whi[3 * FDIM * FDIM];
__device__ __align__(128) __nv_bfloat16 g_Wlo[3 * FDIM * FDIM];

// ---------------------------------------------------------------------------
// helpers
// ---------------------------------------------------------------------------
__device__ __forceinline__ unsigned smem_u32(const void* p) {
    unsigned a;
    asm("{ .reg .u64 t; cvta.to.shared.u64 t, %1; cvt.u32.u64 %0, t; }"
        : "=r"(a) : "l"(p));
    return a;
}
__device__ __forceinline__ unsigned pbf2(float lo, float hi) {
    unsigned r;
    asm("cvt.rn.bf16x2.f32 %0, %1, %2;" : "=r"(r) : "f"(hi), "f"(lo));
    return r;
}
__device__ __forceinline__ void ldsm4(unsigned* r, unsigned addr) {
    asm volatile("ldmatrix.sync.aligned.m8n8.x4.shared.b16 {%0,%1,%2,%3}, [%4];"
                 : "=r"(r[0]), "=r"(r[1]), "=r"(r[2]), "=r"(r[3]) : "r"(addr));
}
__device__ __forceinline__ void mma_bf16(float* c, const unsigned* a,
                                         const unsigned* b) {
    asm volatile(
        "mma.sync.aligned.m16n8k16.row.col.f32.bf16.bf16.f32 "
        "{%0,%1,%2,%3}, {%4,%5,%6,%7}, {%8,%9}, {%0,%1,%2,%3};"
        : "+f"(c[0]), "+f"(c[1]), "+f"(c[2]), "+f"(c[3])
        : "r"(a[0]), "r"(a[1]), "r"(a[2]), "r"(a[3]), "r"(b[0]), "r"(b[1]));
}

// ---------------------------------------------------------------------------
// Zero the aggregation buffers (plain stores, R7 version)
// ---------------------------------------------------------------------------
__global__ void zero_kernel() {
    size_t n = ((size_t)2 * N_NODES * FDIM) / 4;
    float4* p = (float4*)g_agg;
    float4 z = make_float4(0.f, 0.f, 0.f, 0.f);
    for (size_t i = (size_t)blockIdx.x * blockDim.x + threadIdx.x; i < n;
         i += (size_t)gridDim.x * blockDim.x)
        p[i] = z;
}

// ---------------------------------------------------------------------------
// Split weights into bf16 hi/lo
// ---------------------------------------------------------------------------
__global__ void wsplit_kernel(const float* __restrict__ Wn,
                              const float* __restrict__ Wi,
                              const float* __restrict__ Wo) {
    int i = blockIdx.x * blockDim.x + threadIdx.x;
    if (i >= 3 * FDIM * FDIM) return;
    const float* W[3] = {Wn, Wi, Wo};
    float w = W[i >> 14][i & 16383];
    __nv_bfloat16 h = __float2bfloat16_rn(w);
    g_Whi[i] = h;
    g_Wlo[i] = __float2bfloat16_rn(w - __bfloat162float(h));
}

// ---------------------------------------------------------------------------
// Project globals: g_gproj[g][j] = dot(G[g], Wg[j]) + bias[j]  (fp32 exact)
// ---------------------------------------------------------------------------
__global__ void gproj_kernel(const float* __restrict__ gf,
                             const float* __restrict__ Wg,
                             const float* __restrict__ bias) {
    __shared__ float s[FDIM];
    int g = blockIdx.x, j = threadIdx.x;
    s[j] = gf[g * FDIM + j];
    __syncthreads();
    const float4* wrow = (const float4*)(Wg + (size_t)j * FDIM);
    float acc = 0.f;
#pragma unroll
    for (int k = 0; k < FDIM / 4; k++) {
        float4 w = wrow[k];
        const float4 a = *(const float4*)&s[k * 4];
        acc += a.x * w.x + a.y * w.y + a.z * w.z + a.w * w.w;
    }
    g_gproj[g * FDIM + j] = acc + bias[j];
}

// ---------------------------------------------------------------------------
// Column-split scatter: pass `half` touches only cols [64*half, 64*half+64)
// of both agg arrays -> 51MB destination set, L2-resident under evict_last.
// 16 lanes per edge (256B contiguous edge read per edge-half).
// ---------------------------------------------------------------------------
__global__ void scatter_half_kernel(const float4* __restrict__ ef,
                                    const int* __restrict__ recv,
                                    const int* __restrict__ send,
                                    int half) {
    long long gtid = (long long)blockIdx.x * blockDim.x + threadIdx.x;
    int e = (int)(gtid >> 4);
    if (e >= N_EDGES) return;
    int l = threadIdx.x & 15;

    unsigned long long pol_last, pol_first;
    asm("createpolicy.fractional.L2::evict_last.b64 %0, 1.0;" : "=l"(pol_last));
    asm("createpolicy.fractional.L2::evict_first.b64 %0, 1.0;" : "=l"(pol_first));

    float4 v;
    asm volatile("ld.global.nc.L2::cache_hint.v4.f32 {%0,%1,%2,%3}, [%4], %5;"
                 : "=f"(v.x), "=f"(v.y), "=f"(v.z), "=f"(v.w)
                 : "l"(&ef[(size_t)e * (FDIM / 4) + half * 16 + l]),
                   "l"(pol_first));
    int r = __ldg(&recv[e]);
    int s = __ldg(&send[e]);
    const int coff = half * 64 + l * 4;
    float* pr = &g_agg[0][(size_t)r * FDIM + coff];
    float* ps = &g_agg[1][(size_t)s * FDIM + coff];
    asm volatile("red.global.add.L2::cache_hint.v4.f32 [%0], {%1,%2,%3,%4}, %5;"
                 :: "l"(pr), "f"(v.x), "f"(v.y), "f"(v.z), "f"(v.w), "l"(pol_last)
                 : "memory");
    asm volatile("red.global.add.L2::cache_hint.v4.f32 [%0], {%1,%2,%3,%4}, %5;"
                 :: "l"(ps), "f"(v.x), "f"(v.y), "f"(v.z), "f"(v.w), "l"(pol_last)
                 : "memory");
}

// ---------------------------------------------------------------------------
// mma.sync bf16 split-3 GEMM (exact R7 WIN version).
// ---------------------------------------------------------------------------
#define TOFF(r, kk) (((r) >> 3) * 512 + ((kk) >> 3) * 128 + ((r)&7) * 16 + ((kk)&7) * 2)

__global__ __launch_bounds__(256, 1) void gemm_kernel(
    const float* __restrict__ node,
    const int* __restrict__ gidx,
    float* __restrict__ out) {
    __shared__ __align__(128) unsigned char sm[4 * 8192];
    const unsigned sA = smem_u32(sm);

    const int tid = threadIdx.x;
    const int wid = tid >> 5, lid = tid & 31;
    const int wm = wid & 3, wn = wid >> 2;
    const int m0 = blockIdx.x * 128;

    const int t8 = lid >> 3, r8 = lid & 7;
    const unsigned aOff = (unsigned)TOFF(wm * 32 + (t8 & 1) * 8 + r8, (t8 >> 1) * 8);
    const unsigned bOff = (unsigned)TOFF(wn * 64 + (t8 >> 1) * 8 + r8, (t8 & 1) * 8);

    const unsigned aHi = sA + aOff;
    const unsigned bHi = sA + 16384 + bOff;

    float acc[2][8][4];
#pragma unroll
    for (int i = 0; i < 2; i++)
#pragma unroll
        for (int j = 0; j < 8; j++)
#pragma unroll
            for (int q = 0; q < 4; q++) acc[i][j][q] = 0.f;

    const float* Asrc[3] = {node, g_agg[0], g_agg[1]};

    const int frow = tid >> 1;
    const int fkh = (tid & 1) * 16;
    int arow_g = m0 + frow;
    if (arow_g >= N_NODES) arow_g = N_NODES - 1;

#pragma unroll 1
    for (int ch = 0; ch < 12; ch++) {
        const int p = ch >> 2;
        const int kc = (ch & 3) * 32;

        __syncthreads();
        {
            const float* ap = Asrc[p] + (size_t)arow_g * FDIM + kc + fkh;
#pragma unroll
            for (int g = 0; g < 2; g++) {
                float4 f0 = *(const float4*)(ap + g * 8);
                float4 f1 = *(const float4*)(ap + g * 8 + 4);
                __nv_bfloat16 h0 = __float2bfloat16_rn(f0.x);
                __nv_bfloat16 h1 = __float2bfloat16_rn(f0.y);
                __nv_bfloat16 h2 = __float2bfloat16_rn(f0.z);
                __nv_bfloat16 h3 = __float2bfloat16_rn(f0.w);
                __nv_bfloat16 h4 = __float2bfloat16_rn(f1.x);
                __nv_bfloat16 h5 = __float2bfloat16_rn(f1.y);
                __nv_bfloat16 h6 = __float2bfloat16_rn(f1.z);
                __nv_bfloat16 h7 = __float2bfloat16_rn(f1.w);
                uint4 vh;
                vh.x = ((unsigned)__bfloat16_as_ushort(h1) << 16) | __bfloat16_as_ushort(h0);
                vh.y = ((unsigned)__bfloat16_as_ushort(h3) << 16) | __bfloat16_as_ushort(h2);
                vh.z = ((unsigned)__bfloat16_as_ushort(h5) << 16) | __bfloat16_as_ushort(h4);
                vh.w = ((unsigned)__bfloat16_as_ushort(h7) << 16) | __bfloat16_as_ushort(h6);
                uint4 vl;
                vl.x = pbf2(f0.x - __bfloat162float(h0), f0.y - __bfloat162float(h1));
                vl.y = pbf2(f0.z - __bfloat162float(h2), f0.w - __bfloat162float(h3));
                vl.z = pbf2(f1.x - __bfloat162float(h4), f1.y - __bfloat162float(h5));
                vl.w = pbf2(f1.z - __bfloat162float(h6), f1.w - __bfloat162float(h7));
                unsigned off = (unsigned)((frow >> 3) * 512 + ((fkh >> 3) + g) * 128 +
                                          (frow & 7) * 16);
                *(uint4*)(sm + off) = vh;
                *(uint4*)(sm + 8192 + off) = vl;
            }
        }
        {
            const unsigned char* bh = (const unsigned char*)g_Whi +
                ((size_t)p * FDIM * FDIM + (size_t)frow * FDIM + kc + fkh) * 2;
            const unsigned char* bl = (const unsigned char*)g_Wlo +
                ((size_t)p * FDIM * FDIM + (size_t)frow * FDIM + kc + fkh) * 2;
#pragma unroll
            for (int g = 0; g < 2; g++) {
                uint4 vh = *(const uint4*)(bh + g * 16);
                uint4 vl = *(const uint4*)(bl + g * 16);
                unsigned off = (unsigned)((frow >> 3) * 512 + ((fkh >> 3) + g) * 128 +
                                          (frow & 7) * 16);
                *(uint4*)(sm + 16384 + off) = vh;
                *(uint4*)(sm + 24576 + off) = vl;
            }
        }
        __syncthreads();

#pragma unroll
        for (int ks = 0; ks < 2; ks++) {
            const unsigned kso = ks * 256;
            unsigned ah[2][4], al[2][4];
            ldsm4(ah[0], aHi + kso);
            ldsm4(ah[1], aHi + 1024 + kso);
            ldsm4(al[0], aHi + 8192 + kso);
            ldsm4(al[1], aHi + 9216 + kso);
#pragma unroll
            for (int np = 0; np < 4; np++) {
                unsigned bh[4], bl[4];
                ldsm4(bh, bHi + np * 1024 + kso);
                ldsm4(bl, bHi + 8192 + np * 1024 + kso);
#pragma unroll
                for (int mt = 0; mt < 2; mt++) {
                    mma_bf16(acc[mt][np * 2], ah[mt], bh);
                    mma_bf16(acc[mt][np * 2 + 1], ah[mt], bh + 2);
                    mma_bf16(acc[mt][np * 2], ah[mt], bl);
                    mma_bf16(acc[mt][np * 2 + 1], ah[mt], bl + 2);
                    mma_bf16(acc[mt][np * 2], al[mt], bh);
                    mma_bf16(acc[mt][np * 2 + 1], al[mt], bh + 2);
                }
            }
        }
    }

    const int quad = lid >> 2, qlane = lid & 3;
#pragma unroll
    for (int mt = 0; mt < 2; mt++) {
        const int r0 = m0 + wm * 32 + mt * 16 + quad;
        const int r1 = r0 + 8;
        const bool ok0 = r0 < N_NODES, ok1 = r1 < N_NODES;
        const float* gp0 = g_gproj + (size_t)(ok0 ? __ldg(&gidx[r0]) : 0) * FDIM;
        const float* gp1 = g_gproj + (size_t)(ok1 ? __ldg(&gidx[r1]) : 0) * FDIM;
#pragma unroll
        for (int nt = 0; nt < 8; nt++) {
            const int col = wn * 64 + nt * 8 + qlane * 2;
            if (ok0) {
                float2 g0 = *(const float2*)(gp0 + col);
                float2 o0 = make_float2(acc[mt][nt][0] + g0.x, acc[mt][nt][1] + g0.y);
                *(float2*)(out + (size_t)r0 * FDIM + col) = o0;
            }
            if (ok1) {
                float2 g1 = *(const float2*)(gp1 + col);
                float2 o1 = make_float2(acc[mt][nt][2] + g1.x, acc[mt][nt][3] + g1.y);
                *(float2*)(out + (size_t)r1 * FDIM + col) = o1;
            }
        }
    }
}

// ---------------------------------------------------------------------------
// Launch
// ---------------------------------------------------------------------------
extern "C" void kernel_launch(void* const* d_in, const int* in_sizes, int n_in,
                              void* d_out, int out_size) {
    const float* node_features   = (const float*)d_in[0];
    const float* edge_features   = (const float*)d_in[1];
    const float* global_features = (const float*)d_in[2];
    const float* W_node     = (const float*)d_in[3];
    const float* W_incoming = (const float*)d_in[4];
    const float* W_outgoing = (const float*)d_in[5];
    const float* W_global   = (const float*)d_in[6];
    const float* bias       = (const float*)d_in[7];
    const int*   receivers  = (const int*)d_in[8];
    const int*   senders    = (const int*)d_in[9];
    const int*   graph_idx  = (const int*)d_in[10];
    float* out = (float*)d_out;

    zero_kernel<<<1024, 256>>>();
    wsplit_kernel<<<(3 * FDIM * FDIM + 255) / 256, 256>>>(W_node, W_incoming,
                                                          W_outgoing);
    gproj_kernel<<<N_GRAPHS, FDIM>>>(global_features, W_global, bias);

    {
        int threads = 256;
        long long total = (long long)N_EDGES * 16;
        int blocks = (int)((total + threads - 1) / threads);
        scatter_half_kernel<<<blocks, threads>>>((const float4*)edge_features,
                                                 receivers, senders, 0);
        scatter_half_kernel<<<blocks, threads>>>((const float4*)edge_features,
                                                 receivers, senders, 1);
    }
    {
        int grid = (N_NODES + 127) / 128;  // 782
        gemm_kernel<<<grid, 256>>>(node_features, graph_idx, out);
    }
}